// round 2
// baseline (speedup 1.0000x reference)
#include <cuda_runtime.h>
#include <cuda_fp16.h>

#define Tn 8192
#define Hn 1024
#define En 8
#define Fn 3584
#define NSLOT (Tn * 2)

#define BM 128
#define BN 64
#define BK 32
#define LDA 40  // halves per row (32 + 8 pad) -> conflict-free mma frag loads
#define LDB 40

// ---- scratch (device globals: allocation-free rule) ----
__device__ float  g_y[NSLOT * Hn];          // 64 MB  per-slot expert outputs
__device__ __half g_hmid[NSLOT * Fn];       // 112 MB intermediate GLU activations
__device__ int    g_counts[En];
__device__ int    g_offsets[En + 1];
__device__ int    g_slot_e[NSLOT];
__device__ int    g_slot_ticket[NSLOT];
__device__ int    g_rowmap[NSLOT];          // compact row -> t*2+k
__device__ float  g_gates[NSLOT];

// ---------------------------------------------------------------------------
__global__ void zero_counts_kernel() {
    if (threadIdx.x < En) g_counts[threadIdx.x] = 0;
}

// one warp per token: fp32 logits, softmax-top2, renormalized gates, ticketing
__global__ void router_kernel(const float* __restrict__ x,
                              const float* __restrict__ rw) {
    __shared__ float s_rw[En * Hn];  // 32 KB
    for (int i = threadIdx.x; i < En * Hn; i += blockDim.x) s_rw[i] = rw[i];
    __syncthreads();

    int warp = threadIdx.x >> 5, lane = threadIdx.x & 31;
    int t = blockIdx.x * 8 + warp;
    if (t >= Tn) return;

    const float* xt = x + (size_t)t * Hn;
    float acc[En];
#pragma unroll
    for (int e = 0; e < En; e++) acc[e] = 0.f;

    for (int h = lane; h < Hn; h += 32) {
        float xv = xt[h];
#pragma unroll
        for (int e = 0; e < En; e++) acc[e] += xv * s_rw[e * Hn + h];
    }
#pragma unroll
    for (int e = 0; e < En; e++)
#pragma unroll
        for (int o = 16; o; o >>= 1) acc[e] += __shfl_xor_sync(0xFFFFFFFFu, acc[e], o);

    if (lane == 0) {
        int i0 = 0; float v0 = acc[0];
#pragma unroll
        for (int e = 1; e < En; e++) if (acc[e] > v0) { v0 = acc[e]; i0 = e; }
        int i1 = -1; float v1 = -3.4e38f;
#pragma unroll
        for (int e = 0; e < En; e++) if (e != i0 && acc[e] > v1) { v1 = acc[e]; i1 = e; }
        // softmax + top2 renorm collapses to exp renorm over the two logits
        float eb = expf(v1 - v0);           // v0 is the global max
        float inv = 1.f / (1.f + eb);
        g_gates[2 * t]     = inv;
        g_gates[2 * t + 1] = eb * inv;
        g_slot_e[2 * t]     = i0;
        g_slot_e[2 * t + 1] = i1;
        g_slot_ticket[2 * t]     = atomicAdd(&g_counts[i0], 1);
        g_slot_ticket[2 * t + 1] = atomicAdd(&g_counts[i1], 1);
    }
}

__global__ void scan_kernel() {
    if (threadIdx.x == 0) {
        int s = 0;
#pragma unroll
        for (int e = 0; e < En; e++) { g_offsets[e] = s; s += g_counts[e]; }
        g_offsets[En] = s;
    }
}

__global__ void scatter_kernel() {
    int i = blockIdx.x * 256 + threadIdx.x;
    if (i < NSLOT) {
        int e = g_slot_e[i];
        g_rowmap[g_offsets[e] + g_slot_ticket[i]] = i;
    }
}

// ---------------------------------------------------------------------------
__device__ __forceinline__ void mma_16816(float c[4], const unsigned a[4],
                                          unsigned b0, unsigned b1) {
    asm volatile(
        "mma.sync.aligned.m16n8k16.row.col.f32.f16.f16.f32 "
        "{%0,%1,%2,%3}, {%4,%5,%6,%7}, {%8,%9}, {%0,%1,%2,%3};\n"
        : "+f"(c[0]), "+f"(c[1]), "+f"(c[2]), "+f"(c[3])
        : "r"(a[0]), "r"(a[1]), "r"(a[2]), "r"(a[3]), "r"(b0), "r"(b1));
}

// GEMM1: hmid[r, n] = silu(X W1^T) * (X V1^T), fused, gathered rows, fp16 out
__global__ __launch_bounds__(256)
void gemm1_kernel(const float* __restrict__ x,
                  const float* __restrict__ w1,
                  const float* __restrict__ v1) {
    int e  = blockIdx.x >> 6;
    int rt = blockIdx.x & 63;
    int cnt = g_counts[e];
    int row0 = rt * BM;
    if (row0 >= cnt) return;
    int off = g_offsets[e];
    int n0  = blockIdx.y * BN;

    __shared__ __half As[BM][LDA];
    __shared__ __half Bw[BN][LDB];
    __shared__ __half Bv[BN][LDB];
    __shared__ int s_tok[BM];

    int tid = threadIdx.x;
    if (tid < BM) {
        int r = row0 + tid;
        int rm = (r < cnt) ? g_rowmap[off + r] : g_rowmap[off];
        s_tok[tid] = rm >> 1;
    }

    int warp = tid >> 5, lane = tid & 31;
    int wr = (warp & 3) * 32;   // warp row offset in tile
    int wc = (warp >> 2) * 32;  // warp col offset in tile

    float accW[2][4][4], accV[2][4][4];
#pragma unroll
    for (int i = 0; i < 2; i++)
#pragma unroll
        for (int j = 0; j < 4; j++)
#pragma unroll
            for (int k = 0; k < 4; k++) { accW[i][j][k] = 0.f; accV[i][j][k] = 0.f; }

    const float* w1e = w1 + (size_t)e * Fn * Hn;
    const float* v1e = v1 + (size_t)e * Fn * Hn;

    for (int k0 = 0; k0 < Hn; k0 += BK) {
        __syncthreads();
        // A: 128x32 fp32 gather -> fp16 smem (4 float4 / thread)
#pragma unroll
        for (int it = 0; it < 4; it++) {
            int lin = tid + it * 256;
            int r = lin >> 3, c4 = lin & 7;
            float4 v = *reinterpret_cast<const float4*>(
                x + (size_t)s_tok[r] * Hn + k0 + c4 * 4);
            *reinterpret_cast<__half2*>(&As[r][c4 * 4])     = __floats2half2_rn(v.x, v.y);
            *reinterpret_cast<__half2*>(&As[r][c4 * 4 + 2]) = __floats2half2_rn(v.z, v.w);
        }
        // B (w1 & v1): 64x32 each (2 float4 / thread each)
#pragma unroll
        for (int it = 0; it < 2; it++) {
            int lin = tid + it * 256;
            int r = lin >> 3, c4 = lin & 7;
            size_t gaddr = (size_t)(n0 + r) * Hn + k0 + c4 * 4;
            float4 vw = *reinterpret_cast<const float4*>(w1e + gaddr);
            float4 vv = *reinterpret_cast<const float4*>(v1e + gaddr);
            *reinterpret_cast<__half2*>(&Bw[r][c4 * 4])     = __floats2half2_rn(vw.x, vw.y);
            *reinterpret_cast<__half2*>(&Bw[r][c4 * 4 + 2]) = __floats2half2_rn(vw.z, vw.w);
            *reinterpret_cast<__half2*>(&Bv[r][c4 * 4])     = __floats2half2_rn(vv.x, vv.y);
            *reinterpret_cast<__half2*>(&Bv[r][c4 * 4 + 2]) = __floats2half2_rn(vv.z, vv.w);
        }
        __syncthreads();

        int rfr = lane >> 2, c2 = (lane & 3) * 2;
#pragma unroll
        for (int ks = 0; ks < 2; ks++) {
            int kk = ks * 16;
            unsigned a[2][4];
#pragma unroll
            for (int mt = 0; mt < 2; mt++) {
                int mr = wr + mt * 16;
                a[mt][0] = *reinterpret_cast<const unsigned*>(&As[mr + rfr][kk + c2]);
                a[mt][1] = *reinterpret_cast<const unsigned*>(&As[mr + rfr + 8][kk + c2]);
                a[mt][2] = *reinterpret_cast<const unsigned*>(&As[mr + rfr][kk + c2 + 8]);
                a[mt][3] = *reinterpret_cast<const unsigned*>(&As[mr + rfr + 8][kk + c2 + 8]);
            }
#pragma unroll
            for (int nt = 0; nt < 4; nt++) {
                int nr = wc + nt * 8 + rfr;
                unsigned bw0 = *reinterpret_cast<const unsigned*>(&Bw[nr][kk + c2]);
                unsigned bw1 = *reinterpret_cast<const unsigned*>(&Bw[nr][kk + c2 + 8]);
                unsigned bv0 = *reinterpret_cast<const unsigned*>(&Bv[nr][kk + c2]);
                unsigned bv1 = *reinterpret_cast<const unsigned*>(&Bv[nr][kk + c2 + 8]);
#pragma unroll
                for (int mt = 0; mt < 2; mt++) {
                    mma_16816(accW[mt][nt], a[mt], bw0, bw1);
                    mma_16816(accV[mt][nt], a[mt], bv0, bv1);
                }
            }
        }
    }

    // epilogue: silu(w) * v -> fp16 hmid
    int rfr = lane >> 2, c2 = (lane & 3) * 2;
#pragma unroll
    for (int mt = 0; mt < 2; mt++) {
#pragma unroll
        for (int nt = 0; nt < 4; nt++) {
            int col = n0 + wc + nt * 8 + c2;
#pragma unroll
            for (int hh = 0; hh < 2; hh++) {
                int rr = row0 + wr + mt * 16 + rfr + hh * 8;
                if (rr < cnt) {
                    float cw0 = accW[mt][nt][hh * 2 + 0], cw1 = accW[mt][nt][hh * 2 + 1];
                    float cv0 = accV[mt][nt][hh * 2 + 0], cv1 = accV[mt][nt][hh * 2 + 1];
                    float h0 = cw0 / (1.f + expf(-cw0)) * cv0;
                    float h1 = cw1 / (1.f + expf(-cw1)) * cv1;
                    *reinterpret_cast<__half2*>(&g_hmid[(size_t)(off + rr) * Fn + col]) =
                        __floats2half2_rn(h0, h1);
                }
            }
        }
    }
}

// GEMM2: y[slot, n] = hmid[r, :] @ w2[e]   (w2 is [F, H], n-major -> transpose in smem)
__global__ __launch_bounds__(256)
void gemm2_kernel(const float* __restrict__ w2) {
    int e  = blockIdx.x >> 6;
    int rt = blockIdx.x & 63;
    int cnt = g_counts[e];
    int row0 = rt * BM;
    if (row0 >= cnt) return;
    int off = g_offsets[e];
    int n0  = blockIdx.y * BN;

    __shared__ __half As[BM][LDA];
    __shared__ __half Bs[BN][LDB];
    __shared__ int s_slot[BM];

    int tid = threadIdx.x;
    if (tid < BM) {
        int r = row0 + tid;
        s_slot[tid] = (r < cnt) ? g_rowmap[off + r] : -1;
    }

    int warp = tid >> 5, lane = tid & 31;
    int wr = (warp & 3) * 32;
    int wc = (warp >> 2) * 32;

    float acc[2][4][4];
#pragma unroll
    for (int i = 0; i < 2; i++)
#pragma unroll
        for (int j = 0; j < 4; j++)
#pragma unroll
            for (int k = 0; k < 4; k++) acc[i][j][k] = 0.f;

    const float* w2e = w2 + (size_t)e * Fn * Hn;

    for (int k0 = 0; k0 < Fn; k0 += BK) {
        __syncthreads();
        // A: hmid fp16 rows (2 uint4 / thread), guard OOB rows with zeros
#pragma unroll
        for (int it = 0; it < 2; it++) {
            int lin = tid + it * 256;
            int r = lin >> 2, c = lin & 3;
            int gr = row0 + r;
            uint4 val = make_uint4(0, 0, 0, 0);
            if (gr < cnt)
                val = *reinterpret_cast<const uint4*>(
                    &g_hmid[(size_t)(off + gr) * Fn + k0 + c * 8]);
            *reinterpret_cast<uint4*>(&As[r][c * 8]) = val;
        }
        // B: w2 tile [32 k][64 n] fp32, transposed into Bs[n][k] fp16
#pragma unroll
        for (int it = 0; it < 4; it++) {
            int lin = tid + it * 256;
            int kr = lin >> 5, nc = (lin & 31) * 2;
            float2 v = *reinterpret_cast<const float2*>(
                w2e + (size_t)(k0 + kr) * Hn + n0 + nc);
            Bs[nc][kr]     = __float2half_rn(v.x);
            Bs[nc + 1][kr] = __float2half_rn(v.y);
        }
        __syncthreads();

        int rfr = lane >> 2, c2 = (lane & 3) * 2;
#pragma unroll
        for (int ks = 0; ks < 2; ks++) {
            int kk = ks * 16;
            unsigned a[2][4];
#pragma unroll
            for (int mt = 0; mt < 2; mt++) {
                int mr = wr + mt * 16;
                a[mt][0] = *reinterpret_cast<const unsigned*>(&As[mr + rfr][kk + c2]);
                a[mt][1] = *reinterpret_cast<const unsigned*>(&As[mr + rfr + 8][kk + c2]);
                a[mt][2] = *reinterpret_cast<const unsigned*>(&As[mr + rfr][kk + c2 + 8]);
                a[mt][3] = *reinterpret_cast<const unsigned*>(&As[mr + rfr + 8][kk + c2 + 8]);
            }
#pragma unroll
            for (int nt = 0; nt < 4; nt++) {
                int nr = wc + nt * 8 + rfr;
                unsigned b0 = *reinterpret_cast<const unsigned*>(&Bs[nr][kk + c2]);
                unsigned b1 = *reinterpret_cast<const unsigned*>(&Bs[nr][kk + c2 + 8]);
#pragma unroll
                for (int mt = 0; mt < 2; mt++) mma_16816(acc[mt][nt], a[mt], b0, b1);
            }
        }
    }

    int rfr = lane >> 2, c2 = (lane & 3) * 2;
#pragma unroll
    for (int mt = 0; mt < 2; mt++) {
#pragma unroll
        for (int nt = 0; nt < 4; nt++) {
            int col = n0 + wc + nt * 8 + c2;
#pragma unroll
            for (int hh = 0; hh < 2; hh++) {
                int lr = wr + mt * 16 + rfr + hh * 8;
                int slot = s_slot[lr];
                if (slot >= 0) {
                    float2 o;
                    o.x = acc[mt][nt][hh * 2 + 0];
                    o.y = acc[mt][nt][hh * 2 + 1];
                    *reinterpret_cast<float2*>(&g_y[(size_t)slot * Hn + col]) = o;
                }
            }
        }
    }
}

// out[t] = g0 * y[2t] + g1 * y[2t+1]   (fixed order -> deterministic)
__global__ void combine_kernel(float* __restrict__ out) {
    int i = blockIdx.x * 256 + threadIdx.x;
    if (i < Tn * (Hn / 4)) {
        int t  = i / (Hn / 4);
        int c4 = i % (Hn / 4);
        float g0 = g_gates[2 * t], g1 = g_gates[2 * t + 1];
        float4 y0 = *reinterpret_cast<const float4*>(&g_y[(size_t)(2 * t) * Hn + c4 * 4]);
        float4 y1 = *reinterpret_cast<const float4*>(&g_y[(size_t)(2 * t + 1) * Hn + c4 * 4]);
        float4 o;
        o.x = g0 * y0.x + g1 * y1.x;
        o.y = g0 * y0.y + g1 * y1.y;
        o.z = g0 * y0.z + g1 * y1.z;
        o.w = g0 * y0.w + g1 * y1.w;
        *reinterpret_cast<float4*>(out + (size_t)i * 4) = o;
    }
}

// ---------------------------------------------------------------------------
extern "C" void kernel_launch(void* const* d_in, const int* in_sizes, int n_in,
                              void* d_out, int out_size) {
    const float* x  = (const float*)d_in[0];   // hidden_states [4,2048,1024]
    const float* rw = (const float*)d_in[1];   // router_w [8,1024]
    const float* w1 = (const float*)d_in[2];   // [8,3584,1024]
    const float* v1 = (const float*)d_in[3];   // [8,3584,1024]
    const float* w2 = (const float*)d_in[4];   // [8,3584,1024]
    float* out = (float*)d_out;

    zero_counts_kernel<<<1, 32>>>();
    router_kernel<<<Tn / 8, 256>>>(x, rw);
    scan_kernel<<<1, 32>>>();
    scatter_kernel<<<(NSLOT + 255) / 256, 256>>>();
    gemm1_kernel<<<dim3(En * (Tn / BM), Fn / BN), 256>>>(x, w1, v1);
    gemm2_kernel<<<dim3(En * (Tn / BM), Hn / BN), 256>>>(w2);
    combine_kernel<<<(Tn * (Hn / 4) + 255) / 256, 256>>>(out);
}

// round 3
// speedup vs baseline: 1.5952x; 1.5952x over previous
#include <cuda_runtime.h>
#include <cuda_fp16.h>

#define Tn 8192
#define Hn 1024
#define En 8
#define Fn 3584
#define F2 (2 * Fn)          // 7168 interleaved w1/v1 rows
#define NSLOT (Tn * 2)

#define BM 128
#define BN 128
#define BK 32
#define LD 40                // half stride: 80B rows, 16B-aligned, conflict-free

// ---- scratch (device globals: allocation-free rule) ----
__device__ __half g_xh[Tn * Hn];           // 16 MB  fp16 tokens
__device__ __half g_w1v1[En * F2 * Hn];    // 117 MB interleaved fp16 w1/v1
__device__ __half g_w2t[En * Hn * Fn];     // 59 MB  transposed fp16 w2
__device__ __half g_hmid[NSLOT * Fn];      // 112 MB GLU activations
__device__ float  g_y[NSLOT * Hn];         // 64 MB  per-slot outputs
__device__ int    g_counts[En];
__device__ int    g_offsets[En + 1];
__device__ int    g_slot_e[NSLOT];
__device__ int    g_slot_ticket[NSLOT];
__device__ int    g_rowmap[NSLOT];
__device__ float  g_gates[NSLOT];

// ---------------------------------------------------------------------------
// pre-cast kernels
__global__ void cast_x_kernel(const float* __restrict__ x) {
    int i = blockIdx.x * 256 + threadIdx.x;          // over Tn*Hn/4
    if (i < Tn * Hn / 4) {
        float4 v = reinterpret_cast<const float4*>(x)[i];
        __half2* o = reinterpret_cast<__half2*>(g_xh + (size_t)i * 4);
        o[0] = __floats2half2_rn(v.x, v.y);
        o[1] = __floats2half2_rn(v.z, v.w);
    }
}

// pack w1,v1 -> g_w1v1[e][2f]=w1[e][f], [2f+1]=v1[e][f]  (fp16)
__global__ void pack_w1v1_kernel(const float* __restrict__ w1,
                                 const float* __restrict__ v1) {
    long i = (long)blockIdx.x * 256 + threadIdx.x;   // over E*F*H/4
    const long N = (long)En * Fn * Hn / 4;
    if (i >= N) return;
    long row = i >> 8;            // 256 float4 per 1024-wide row
    int  c   = (int)(i & 255);
    long e = row / Fn, f = row % Fn;
    float4 a = reinterpret_cast<const float4*>(w1)[i];
    float4 b = reinterpret_cast<const float4*>(v1)[i];
    __half2* ow = reinterpret_cast<__half2*>(g_w1v1 + ((e * F2 + 2 * f) * Hn) + c * 4);
    __half2* ov = reinterpret_cast<__half2*>(g_w1v1 + ((e * F2 + 2 * f + 1) * Hn) + c * 4);
    ow[0] = __floats2half2_rn(a.x, a.y); ow[1] = __floats2half2_rn(a.z, a.w);
    ov[0] = __floats2half2_rn(b.x, b.y); ov[1] = __floats2half2_rn(b.z, b.w);
}

// transpose w2 [E][F][H] fp32 -> g_w2t [E][H][F] fp16
__global__ void transpose_w2_kernel(const float* __restrict__ w2) {
    __shared__ float t[32][33];
    int e = blockIdx.z;
    int f0 = blockIdx.x * 32, h0 = blockIdx.y * 32;
    int tx = threadIdx.x, ty = threadIdx.y;          // (32, 8)
    const float* src = w2 + ((long)e * Fn + f0) * Hn + h0;
#pragma unroll
    for (int r = 0; r < 32; r += 8) t[ty + r][tx] = src[(long)(ty + r) * Hn + tx];
    __syncthreads();
    __half* dst = g_w2t + ((long)e * Hn + h0) * Fn + f0;
#pragma unroll
    for (int r = 0; r < 32; r += 8)
        dst[(long)(ty + r) * Fn + tx] = __float2half_rn(t[tx][ty + r]);
}

// ---------------------------------------------------------------------------
__global__ void zero_counts_kernel() {
    if (threadIdx.x < En) g_counts[threadIdx.x] = 0;
}

__global__ void router_kernel(const float* __restrict__ x,
                              const float* __restrict__ rw) {
    __shared__ float s_rw[En * Hn];
    for (int i = threadIdx.x; i < En * Hn; i += blockDim.x) s_rw[i] = rw[i];
    __syncthreads();

    int warp = threadIdx.x >> 5, lane = threadIdx.x & 31;
    int t = blockIdx.x * 8 + warp;
    if (t >= Tn) return;

    const float* xt = x + (size_t)t * Hn;
    float acc[En];
#pragma unroll
    for (int e = 0; e < En; e++) acc[e] = 0.f;
    for (int h = lane; h < Hn; h += 32) {
        float xv = xt[h];
#pragma unroll
        for (int e = 0; e < En; e++) acc[e] += xv * s_rw[e * Hn + h];
    }
#pragma unroll
    for (int e = 0; e < En; e++)
#pragma unroll
        for (int o = 16; o; o >>= 1) acc[e] += __shfl_xor_sync(0xFFFFFFFFu, acc[e], o);

    if (lane == 0) {
        int i0 = 0; float v0 = acc[0];
#pragma unroll
        for (int e = 1; e < En; e++) if (acc[e] > v0) { v0 = acc[e]; i0 = e; }
        int i1 = -1; float v1 = -3.4e38f;
#pragma unroll
        for (int e = 0; e < En; e++) if (e != i0 && acc[e] > v1) { v1 = acc[e]; i1 = e; }
        float eb = expf(v1 - v0);
        float inv = 1.f / (1.f + eb);
        g_gates[2 * t]     = inv;
        g_gates[2 * t + 1] = eb * inv;
        g_slot_e[2 * t]     = i0;
        g_slot_e[2 * t + 1] = i1;
        g_slot_ticket[2 * t]     = atomicAdd(&g_counts[i0], 1);
        g_slot_ticket[2 * t + 1] = atomicAdd(&g_counts[i1], 1);
    }
}

__global__ void scan_kernel() {
    if (threadIdx.x == 0) {
        int s = 0;
#pragma unroll
        for (int e = 0; e < En; e++) { g_offsets[e] = s; s += g_counts[e]; }
        g_offsets[En] = s;
    }
}

__global__ void scatter_kernel() {
    int i = blockIdx.x * 256 + threadIdx.x;
    if (i < NSLOT) {
        int e = g_slot_e[i];
        g_rowmap[g_offsets[e] + g_slot_ticket[i]] = i;
    }
}

// ---------------------------------------------------------------------------
__device__ __forceinline__ void mma_16816(float c[4], const unsigned a[4],
                                          unsigned b0, unsigned b1) {
    asm volatile(
        "mma.sync.aligned.m16n8k16.row.col.f32.f16.f16.f32 "
        "{%0,%1,%2,%3}, {%4,%5,%6,%7}, {%8,%9}, {%0,%1,%2,%3};\n"
        : "+f"(c[0]), "+f"(c[1]), "+f"(c[2]), "+f"(c[3])
        : "r"(a[0]), "r"(a[1]), "r"(a[2]), "r"(a[3]), "r"(b0), "r"(b1));
}

__device__ __forceinline__ void cp16(unsigned sdst, const void* g) {
    asm volatile("cp.async.cg.shared.global [%0], [%1], 16;\n"
                 :: "r"(sdst), "l"(g));
}
__device__ __forceinline__ void cp16p(unsigned sdst, const void* g, bool valid) {
    int sz = valid ? 16 : 0;
    asm volatile("cp.async.cg.shared.global [%0], [%1], 16, %2;\n"
                 :: "r"(sdst), "l"(g), "r"(sz));
}

// GEMM1: hmid = silu(X W1^T) * (X V1^T) against interleaved fp16 B, fp16 out
__global__ __launch_bounds__(256)
void gemm1_kernel() {
    int e  = blockIdx.x >> 6;
    int rt = blockIdx.x & 63;
    int cnt = g_counts[e];
    int row0 = rt * BM;
    if (row0 >= cnt) return;
    int off = g_offsets[e];
    int n0  = blockIdx.y * BN;

    __shared__ __half As[2][BM * LD];
    __shared__ __half Bs[2][BN * LD];
    __shared__ int s_tok[BM];

    int tid = threadIdx.x;
    if (tid < BM) {
        int r = row0 + tid;
        s_tok[tid] = g_rowmap[off + (r < cnt ? r : 0)] >> 1;
    }
    __syncthreads();

    const __half* Bsrc = g_w1v1 + (long)e * F2 * Hn;

    int cr = tid >> 2, cq = tid & 3;   // chunk row / quarter (4×16B per 64B row)

    auto load_stage = [&](int kt, int buf) {
        int k0 = kt * BK;
#pragma unroll
        for (int it = 0; it < 2; it++) {
            int r = cr + it * 64;
            unsigned d = (unsigned)__cvta_generic_to_shared(&As[buf][r * LD + cq * 8]);
            cp16(d, g_xh + (long)s_tok[r] * Hn + k0 + cq * 8);
        }
#pragma unroll
        for (int it = 0; it < 2; it++) {
            int r = cr + it * 64;
            unsigned d = (unsigned)__cvta_generic_to_shared(&Bs[buf][r * LD + cq * 8]);
            cp16(d, Bsrc + (long)(n0 + r) * Hn + k0 + cq * 8);
        }
        asm volatile("cp.async.commit_group;\n");
    };

    int warp = tid >> 5, lane = tid & 31;
    int wr = (warp & 1) * 64, wc = (warp >> 1) * 32;
    int rfr = lane >> 2, c2 = (lane & 3) * 2;

    float acc[4][4][4];
#pragma unroll
    for (int i = 0; i < 4; i++)
#pragma unroll
        for (int j = 0; j < 4; j++)
#pragma unroll
            for (int k = 0; k < 4; k++) acc[i][j][k] = 0.f;

    load_stage(0, 0);
    const int NK = Hn / BK;   // 32
    for (int kt = 0; kt < NK; kt++) {
        int buf = kt & 1;
        if (kt + 1 < NK) {
            load_stage(kt + 1, buf ^ 1);
            asm volatile("cp.async.wait_group 1;\n");
        } else {
            asm volatile("cp.async.wait_group 0;\n");
        }
        __syncthreads();
        const __half* A = As[buf];
        const __half* B = Bs[buf];
#pragma unroll
        for (int ks = 0; ks < 2; ks++) {
            int kk = ks * 16;
            unsigned a[4][4];
#pragma unroll
            for (int mt = 0; mt < 4; mt++) {
                int mr = wr + mt * 16;
                a[mt][0] = *(const unsigned*)&A[(mr + rfr) * LD + kk + c2];
                a[mt][1] = *(const unsigned*)&A[(mr + rfr + 8) * LD + kk + c2];
                a[mt][2] = *(const unsigned*)&A[(mr + rfr) * LD + kk + c2 + 8];
                a[mt][3] = *(const unsigned*)&A[(mr + rfr + 8) * LD + kk + c2 + 8];
            }
#pragma unroll
            for (int nt = 0; nt < 4; nt++) {
                int nr = wc + nt * 8 + rfr;
                unsigned b0 = *(const unsigned*)&B[nr * LD + kk + c2];
                unsigned b1 = *(const unsigned*)&B[nr * LD + kk + c2 + 8];
#pragma unroll
                for (int mt = 0; mt < 4; mt++) mma_16816(acc[mt][nt], a[mt], b0, b1);
            }
        }
        __syncthreads();
    }

    // epilogue: even col = w, odd col = v of the same f -> silu(w)*v
#pragma unroll
    for (int mt = 0; mt < 4; mt++) {
#pragma unroll
        for (int nt = 0; nt < 4; nt++) {
            int f = ((n0 + wc + nt * 8) >> 1) + (lane & 3);
#pragma unroll
            for (int hh = 0; hh < 2; hh++) {
                int rr = row0 + wr + mt * 16 + rfr + hh * 8;
                if (rr < cnt) {
                    float w = acc[mt][nt][hh * 2 + 0];
                    float v = acc[mt][nt][hh * 2 + 1];
                    float h = w / (1.f + expf(-w)) * v;
                    g_hmid[(long)(off + rr) * Fn + f] = __float2half_rn(h);
                }
            }
        }
    }
}

// GEMM2: y[slot] = hmid @ w2  (B = g_w2t, K-major fp16)
__global__ __launch_bounds__(256)
void gemm2_kernel() {
    int e  = blockIdx.x >> 6;
    int rt = blockIdx.x & 63;
    int cnt = g_counts[e];
    int row0 = rt * BM;
    if (row0 >= cnt) return;
    int off = g_offsets[e];
    int n0  = blockIdx.y * BN;

    __shared__ __half As[2][BM * LD];
    __shared__ __half Bs[2][BN * LD];
    __shared__ int s_slot[BM];

    int tid = threadIdx.x;
    if (tid < BM) {
        int r = row0 + tid;
        s_slot[tid] = (r < cnt) ? g_rowmap[off + r] : -1;
    }
    __syncthreads();

    const __half* Bsrc = g_w2t + (long)e * Hn * Fn;
    const __half* Asrc = g_hmid + (long)off * Fn;

    int cr = tid >> 2, cq = tid & 3;

    auto load_stage = [&](int kt, int buf) {
        int k0 = kt * BK;
#pragma unroll
        for (int it = 0; it < 2; it++) {
            int r = cr + it * 64;
            unsigned d = (unsigned)__cvta_generic_to_shared(&As[buf][r * LD + cq * 8]);
            cp16p(d, Asrc + (long)(row0 + r) * Fn + k0 + cq * 8, row0 + r < cnt);
        }
#pragma unroll
        for (int it = 0; it < 2; it++) {
            int r = cr + it * 64;
            unsigned d = (unsigned)__cvta_generic_to_shared(&Bs[buf][r * LD + cq * 8]);
            cp16(d, Bsrc + (long)(n0 + r) * Fn + k0 + cq * 8);
        }
        asm volatile("cp.async.commit_group;\n");
    };

    int warp = tid >> 5, lane = tid & 31;
    int wr = (warp & 1) * 64, wc = (warp >> 1) * 32;
    int rfr = lane >> 2, c2 = (lane & 3) * 2;

    float acc[4][4][4];
#pragma unroll
    for (int i = 0; i < 4; i++)
#pragma unroll
        for (int j = 0; j < 4; j++)
#pragma unroll
            for (int k = 0; k < 4; k++) acc[i][j][k] = 0.f;

    load_stage(0, 0);
    const int NK = Fn / BK;   // 112
    for (int kt = 0; kt < NK; kt++) {
        int buf = kt & 1;
        if (kt + 1 < NK) {
            load_stage(kt + 1, buf ^ 1);
            asm volatile("cp.async.wait_group 1;\n");
        } else {
            asm volatile("cp.async.wait_group 0;\n");
        }
        __syncthreads();
        const __half* A = As[buf];
        const __half* B = Bs[buf];
#pragma unroll
        for (int ks = 0; ks < 2; ks++) {
            int kk = ks * 16;
            unsigned a[4][4];
#pragma unroll
            for (int mt = 0; mt < 4; mt++) {
                int mr = wr + mt * 16;
                a[mt][0] = *(const unsigned*)&A[(mr + rfr) * LD + kk + c2];
                a[mt][1] = *(const unsigned*)&A[(mr + rfr + 8) * LD + kk + c2];
                a[mt][2] = *(const unsigned*)&A[(mr + rfr) * LD + kk + c2 + 8];
                a[mt][3] = *(const unsigned*)&A[(mr + rfr + 8) * LD + kk + c2 + 8];
            }
#pragma unroll
            for (int nt = 0; nt < 4; nt++) {
                int nr = wc + nt * 8 + rfr;
                unsigned b0 = *(const unsigned*)&B[nr * LD + kk + c2];
                unsigned b1 = *(const unsigned*)&B[nr * LD + kk + c2 + 8];
#pragma unroll
                for (int mt = 0; mt < 4; mt++) mma_16816(acc[mt][nt], a[mt], b0, b1);
            }
        }
        __syncthreads();
    }

#pragma unroll
    for (int mt = 0; mt < 4; mt++) {
#pragma unroll
        for (int nt = 0; nt < 4; nt++) {
            int col = n0 + wc + nt * 8 + c2;
#pragma unroll
            for (int hh = 0; hh < 2; hh++) {
                int slot = s_slot[wr + mt * 16 + rfr + hh * 8];
                if (slot >= 0) {
                    float2 o;
                    o.x = acc[mt][nt][hh * 2 + 0];
                    o.y = acc[mt][nt][hh * 2 + 1];
                    *reinterpret_cast<float2*>(&g_y[(size_t)slot * Hn + col]) = o;
                }
            }
        }
    }
}

// out[t] = g0 * y[2t] + g1 * y[2t+1]
__global__ void combine_kernel(float* __restrict__ out) {
    int i = blockIdx.x * 256 + threadIdx.x;
    if (i < Tn * (Hn / 4)) {
        int t  = i / (Hn / 4);
        int c4 = i % (Hn / 4);
        float g0 = g_gates[2 * t], g1 = g_gates[2 * t + 1];
        float4 y0 = *reinterpret_cast<const float4*>(&g_y[(size_t)(2 * t) * Hn + c4 * 4]);
        float4 y1 = *reinterpret_cast<const float4*>(&g_y[(size_t)(2 * t + 1) * Hn + c4 * 4]);
        float4 o;
        o.x = g0 * y0.x + g1 * y1.x;
        o.y = g0 * y0.y + g1 * y1.y;
        o.z = g0 * y0.z + g1 * y1.z;
        o.w = g0 * y0.w + g1 * y1.w;
        *reinterpret_cast<float4*>(out + (size_t)i * 4) = o;
    }
}

// ---------------------------------------------------------------------------
extern "C" void kernel_launch(void* const* d_in, const int* in_sizes, int n_in,
                              void* d_out, int out_size) {
    const float* x  = (const float*)d_in[0];
    const float* rw = (const float*)d_in[1];
    const float* w1 = (const float*)d_in[2];
    const float* v1 = (const float*)d_in[3];
    const float* w2 = (const float*)d_in[4];
    float* out = (float*)d_out;

    cast_x_kernel<<<Tn * Hn / 4 / 256, 256>>>(x);
    pack_w1v1_kernel<<<(int)((long)En * Fn * Hn / 4 / 256), 256>>>(w1, v1);
    transpose_w2_kernel<<<dim3(Fn / 32, Hn / 32, En), dim3(32, 8)>>>(w2);

    zero_counts_kernel<<<1, 32>>>();
    router_kernel<<<Tn / 8, 256>>>(x, rw);
    scan_kernel<<<1, 32>>>();
    scatter_kernel<<<(NSLOT + 255) / 256, 256>>>();

    gemm1_kernel<<<dim3(En * (Tn / BM), F2 / BN), 256>>>();
    gemm2_kernel<<<dim3(En * (Tn / BM), Hn / BN), 256>>>();
    combine_kernel<<<(Tn * (Hn / 4) + 255) / 256, 256>>>(out);
}